// round 3
// baseline (speedup 1.0000x reference)
#include <cuda_runtime.h>
#include <math.h>
#include <stdint.h>

#define NN 20000
#define TT 20
#define FF 128
#define HH 128
#define GHD 128
#define NHEADS 4
#define NCLS 10
#define EE 640000
#define EN (EE + NN)

// ---------------- scratch (device globals: allocation-free rule) ----------------
__device__ float g_hcat[NN * 256];
__device__ float g_xh1[NN * 512];
__device__ float g_al1s[NN * 4];
__device__ float g_al1d[NN * 4];
__device__ float g_ee1[EN * 4];
__device__ float g_den1[NN * 4];
__device__ float g_agg1[NN * 512];
__device__ float g_xh2[NN * 128];
__device__ float g_al2s[NN];
__device__ float g_al2d[NN];
__device__ float g_ee2[EN];
__device__ float g_den2[NN];
__device__ float g_agg2[NN * 128];

__device__ __forceinline__ float sigf(float x) { return 1.0f / (1.0f + expf(-x)); }
__device__ __forceinline__ float lrelu(float x) { return x > 0.0f ? x : 0.2f * x; }
__device__ __forceinline__ void red_add_v4(float* p, float a, float b, float c, float d) {
    asm volatile("red.global.add.v4.f32 [%0], {%1,%2,%3,%4};"
                 :: "l"(p), "f"(a), "f"(b), "f"(c), "f"(d) : "memory");
}

// ---------------- zero the accumulated buffers ----------------
__global__ void zero_scratch() {
    const int stride = gridDim.x * blockDim.x;
    const int t0 = blockIdx.x * blockDim.x + threadIdx.x;
    for (int i = t0; i < NN * 512; i += stride) g_agg1[i] = 0.0f;
    for (int i = t0; i < NN * 128; i += stride) g_agg2[i] = 0.0f;
    for (int i = t0; i < NN * 4;   i += stride) g_den1[i] = 0.0f;
    for (int i = t0; i < NN;       i += stride) g_den2[i] = 0.0f;
}

// ---------------- fused BiLSTM ----------------
// Block: 32 sequences, 256 threads. Per step: gates[32][512] = [x_t|h][32][256] @ W^T.
// W (Wih|Whh) streamed from L2 through smem in K-chunks of 16.
// Thread (tr=tid>>6, tc=tid&63): rows tr*8..+7, cols tc+64j (j=0..7).
// Gate layout means thread owns i,f,g,o for hidden cols {tc, tc+64} -> LSTM cell math
// fully register-resident per thread.
#define LSTM_SMEM ((256 * 33 + 512 * 17) * 4)

__global__ void __launch_bounds__(256, 2) lstm_kernel(
    const float* __restrict__ x, const int* __restrict__ lengths,
    const float* __restrict__ Wih_f, const float* __restrict__ Whh_f, const float* __restrict__ b_f,
    const float* __restrict__ Wih_b, const float* __restrict__ Whh_b, const float* __restrict__ b_b)
{
    extern __shared__ float sm[];
    float* A_s = sm;              // [256][33]  k-major (k<128: x_t, k>=128: h)
    float* B_s = sm + 256 * 33;   // [512][17]  c-major chunk of W
    __shared__ int len_s[32];

    const int dir = blockIdx.y;
    const float* __restrict__ Wih = dir ? Wih_b : Wih_f;
    const float* __restrict__ Whh = dir ? Whh_b : Whh_f;
    const float* __restrict__ bb  = dir ? b_b  : b_f;
    const int seq0 = blockIdx.x * 32;
    const int tid = threadIdx.x;
    const int tr = tid >> 6, tc = tid & 63;

    if (tid < 32) len_s[tid] = lengths[seq0 + tid];
    for (int i = tid; i < 128 * 33; i += 256) A_s[128 * 33 + i] = 0.0f;  // h0 = 0

    float bj[8];
#pragma unroll
    for (int j = 0; j < 8; j++) bj[j] = bb[tc + 64 * j];

    float cst[8][2], hreg[8][2];
#pragma unroll
    for (int i = 0; i < 8; i++) { cst[i][0] = cst[i][1] = 0.0f; hreg[i][0] = hreg[i][1] = 0.0f; }

    __syncthreads();

    for (int t = 0; t < TT; t++) {
        // load x_t tile (row-specific time index for reversed direction)
#pragma unroll
        for (int p = 0; p < 4; p++) {
            const int r = p * 8 + (tid >> 5);
            const int k4 = tid & 31;
            const int len = len_s[r];
            const int ttv = dir ? max(len - 1 - t, 0) : t;
            const float4 v = *(const float4*)(x + ((size_t)(seq0 + r) * TT + ttv) * FF + k4 * 4);
            A_s[(k4 * 4 + 0) * 33 + r] = v.x;
            A_s[(k4 * 4 + 1) * 33 + r] = v.y;
            A_s[(k4 * 4 + 2) * 33 + r] = v.z;
            A_s[(k4 * 4 + 3) * 33 + r] = v.w;
        }
        float acc[8][8];
#pragma unroll
        for (int i = 0; i < 8; i++)
#pragma unroll
            for (int j = 0; j < 8; j++) acc[i][j] = bj[j];
        __syncthreads();

        for (int kc = 0; kc < 16; kc++) {
            const int k0 = kc * 16;
            const float* __restrict__ Ws = (k0 < 128) ? Wih : Whh;
            const int kw = k0 & 127;
            const int q = tid & 3, cb = tid >> 2;
#pragma unroll
            for (int cc = 0; cc < 8; cc++) {
                const int c = cb + 64 * cc;
                const float4 w4 = *(const float4*)(Ws + c * 128 + kw + q * 4);
                B_s[c * 17 + q * 4 + 0] = w4.x;
                B_s[c * 17 + q * 4 + 1] = w4.y;
                B_s[c * 17 + q * 4 + 2] = w4.z;
                B_s[c * 17 + q * 4 + 3] = w4.w;
            }
            __syncthreads();
#pragma unroll
            for (int kk = 0; kk < 16; kk++) {
                float av[8], bv[8];
#pragma unroll
                for (int i = 0; i < 8; i++) av[i] = A_s[(k0 + kk) * 33 + tr * 8 + i];
#pragma unroll
                for (int j = 0; j < 8; j++) bv[j] = B_s[(tc + 64 * j) * 17 + kk];
#pragma unroll
                for (int i = 0; i < 8; i++)
#pragma unroll
                    for (int j = 0; j < 8; j++) acc[i][j] = fmaf(av[i], bv[j], acc[i][j]);
            }
            __syncthreads();
        }

        // LSTM cell (torch gate order i,f,g,o), masked update
#pragma unroll
        for (int i = 0; i < 8; i++) {
            const bool m = t < len_s[tr * 8 + i];
#pragma unroll
            for (int p = 0; p < 2; p++) {
                const float ig = sigf(acc[i][0 + p]);
                const float fg = sigf(acc[i][2 + p]);
                const float gg = tanhf(acc[i][4 + p]);
                const float og = sigf(acc[i][6 + p]);
                const float cn = fg * cst[i][p] + ig * gg;
                const float hn = og * tanhf(cn);
                if (m) { cst[i][p] = cn; hreg[i][p] = hn; }
            }
        }
        // publish h for next step (disjoint from x-region; ordered by next step's barrier)
#pragma unroll
        for (int i = 0; i < 8; i++)
#pragma unroll
            for (int p = 0; p < 2; p++)
                A_s[(128 + tc + 64 * p) * 33 + tr * 8 + i] = hreg[i][p];
    }

#pragma unroll
    for (int i = 0; i < 8; i++)
#pragma unroll
        for (int p = 0; p < 2; p++)
            g_hcat[(size_t)(seq0 + tr * 8 + i) * 256 + dir * 128 + tc + 64 * p] = hreg[i][p];
}

// ---------------- generic 32-row SGEMM: C[N][COLS] = A[N][KTOT] @ W[COLS][KTOT]^T ----------------
template <int COLS, int KTOT>
__global__ void __launch_bounds__(256, 2) sgemm32_kernel(
    const float* __restrict__ A, const float* __restrict__ W, float* __restrict__ C)
{
    constexpr int TN = COLS / 64;
    extern __shared__ float sm[];
    float* A_s = sm;              // [KTOT][33]
    float* B_s = sm + KTOT * 33;  // [COLS][17]
    const int tid = threadIdx.x;
    const int tr = tid >> 6, tc = tid & 63;
    const int row0 = blockIdx.x * 32;

    constexpr int K4 = KTOT / 4;
    for (int idx = tid; idx < 32 * K4; idx += 256) {
        const int r = idx / K4, k4 = idx % K4;
        const float4 v = *(const float4*)(A + (size_t)(row0 + r) * KTOT + k4 * 4);
        A_s[(k4 * 4 + 0) * 33 + r] = v.x;
        A_s[(k4 * 4 + 1) * 33 + r] = v.y;
        A_s[(k4 * 4 + 2) * 33 + r] = v.z;
        A_s[(k4 * 4 + 3) * 33 + r] = v.w;
    }
    float acc[8][TN];
#pragma unroll
    for (int i = 0; i < 8; i++)
#pragma unroll
        for (int j = 0; j < TN; j++) acc[i][j] = 0.0f;

    for (int kc = 0; kc < KTOT / 16; kc++) {
        const int k0 = kc * 16;
        const int q = tid & 3, cb = tid >> 2;
#pragma unroll
        for (int cc = 0; cc < COLS / 64; cc++) {
            const int c = cb + 64 * cc;
            const float4 w4 = *(const float4*)(W + (size_t)c * KTOT + k0 + q * 4);
            B_s[c * 17 + q * 4 + 0] = w4.x;
            B_s[c * 17 + q * 4 + 1] = w4.y;
            B_s[c * 17 + q * 4 + 2] = w4.z;
            B_s[c * 17 + q * 4 + 3] = w4.w;
        }
        __syncthreads();
#pragma unroll
        for (int kk = 0; kk < 16; kk++) {
            float av[8], bv[TN];
#pragma unroll
            for (int i = 0; i < 8; i++) av[i] = A_s[(k0 + kk) * 33 + tr * 8 + i];
#pragma unroll
            for (int j = 0; j < TN; j++) bv[j] = B_s[(tc + 64 * j) * 17 + kk];
#pragma unroll
            for (int i = 0; i < 8; i++)
#pragma unroll
                for (int j = 0; j < TN; j++) acc[i][j] = fmaf(av[i], bv[j], acc[i][j]);
        }
        __syncthreads();
    }
#pragma unroll
    for (int i = 0; i < 8; i++)
#pragma unroll
        for (int j = 0; j < TN; j++)
            C[(size_t)(row0 + tr * 8 + i) * COLS + tc + 64 * j] = acc[i][j];
}

// ---------------- GAT attention-logit projections (warp per (node, head)) ----------------
template <int NH>
__global__ void gat_al(const float* __restrict__ xh, const float* __restrict__ asrc,
                       const float* __restrict__ adst, float* __restrict__ als,
                       float* __restrict__ ald)
{
    const int w = (blockIdx.x * blockDim.x + threadIdx.x) >> 5;
    const int lane = threadIdx.x & 31;
    if (w >= NN * NH) return;
    const int n = w / NH, h = w % NH;
    const float4 v  = *(const float4*)(xh + (size_t)n * (NH * GHD) + h * GHD + lane * 4);
    const float4 s4 = *(const float4*)(asrc + h * GHD + lane * 4);
    const float4 d4 = *(const float4*)(adst + h * GHD + lane * 4);
    float s = v.x * s4.x + v.y * s4.y + v.z * s4.z + v.w * s4.w;
    float d = v.x * d4.x + v.y * d4.y + v.z * d4.z + v.w * d4.w;
#pragma unroll
    for (int o = 16; o > 0; o >>= 1) {
        s += __shfl_xor_sync(0xffffffffu, s, o);
        d += __shfl_xor_sync(0xffffffffu, d, o);
    }
    if (lane == 0) { als[w] = s; ald[w] = d; }
}

// ---------------- edge softmax numerator + denominator (layer 1, 4 heads) ----------------
__global__ void edge_b4(const int* __restrict__ ei) {
    const int e = blockIdx.x * blockDim.x + threadIdx.x;
    if (e >= EN) return;
    int s, d;
    if (e < EE) { s = ei[e]; d = ei[EE + e]; } else { s = d = e - EE; }
    const float4 as = *(const float4*)(g_al1s + (size_t)s * 4);
    const float4 ad = *(const float4*)(g_al1d + (size_t)d * 4);
    float4 ev;
    ev.x = expf(lrelu(as.x + ad.x));
    ev.y = expf(lrelu(as.y + ad.y));
    ev.z = expf(lrelu(as.z + ad.z));
    ev.w = expf(lrelu(as.w + ad.w));
    *(float4*)(g_ee1 + (size_t)e * 4) = ev;
    red_add_v4(g_den1 + (size_t)d * 4, ev.x, ev.y, ev.z, ev.w);
}

// ---------------- weighted aggregate (layer 1): warp per (edge, head) ----------------
__global__ void edge_c4(const int* __restrict__ ei) {
    const int w = (blockIdx.x * blockDim.x + threadIdx.x) >> 5;
    const int lane = threadIdx.x & 31;
    if (w >= EN * NHEADS) return;
    const int e = w >> 2, h = w & 3;
    int s, d;
    if (e < EE) { s = ei[e]; d = ei[EE + e]; } else { s = d = e - EE; }
    const float alpha = g_ee1[(size_t)e * 4 + h] / (g_den1[(size_t)d * 4 + h] + 1e-16f);
    const float4 v = *(const float4*)(g_xh1 + (size_t)s * 512 + h * GHD + lane * 4);
    red_add_v4(g_agg1 + (size_t)d * 512 + h * GHD + lane * 4,
               v.x * alpha, v.y * alpha, v.z * alpha, v.w * alpha);
}

// ---------------- layer 2 (1 head) ----------------
__global__ void edge_b1(const int* __restrict__ ei) {
    const int e = blockIdx.x * blockDim.x + threadIdx.x;
    if (e >= EN) return;
    int s, d;
    if (e < EE) { s = ei[e]; d = ei[EE + e]; } else { s = d = e - EE; }
    const float ev = expf(lrelu(g_al2s[s] + g_al2d[d]));
    g_ee2[e] = ev;
    atomicAdd(g_den2 + d, ev);
}

__global__ void edge_c1(const int* __restrict__ ei) {
    const int w = (blockIdx.x * blockDim.x + threadIdx.x) >> 5;
    const int lane = threadIdx.x & 31;
    if (w >= EN) return;
    int s, d;
    if (w < EE) { s = ei[w]; d = ei[EE + w]; } else { s = d = w - EE; }
    const float alpha = g_ee2[w] / (g_den2[d] + 1e-16f);
    const float4 v = *(const float4*)(g_xh2 + (size_t)s * 128 + lane * 4);
    red_add_v4(g_agg2 + (size_t)d * 128 + lane * 4,
               v.x * alpha, v.y * alpha, v.z * alpha, v.w * alpha);
}

// ---------------- bias + relu (in place) ----------------
__global__ void bias_relu(float* __restrict__ buf, const float* __restrict__ bias,
                          int total, int colmask) {
    const int i = blockIdx.x * blockDim.x + threadIdx.x;
    if (i >= total) return;
    buf[i] = fmaxf(buf[i] + bias[i & colmask], 0.0f);
}

// ---------------- final FC: out[n][c] = h2[n] . Wfc[c] + bfc[c] ----------------
__global__ void fc_kernel(const float* __restrict__ Wfc, const float* __restrict__ bfc,
                          float* __restrict__ out) {
    const int idx = blockIdx.x * blockDim.x + threadIdx.x;
    if (idx >= NN * NCLS) return;
    const int n = idx / NCLS, c = idx - n * NCLS;
    const float* hr = g_agg2 + (size_t)n * 128;
    const float* wr = Wfc + c * 128;
    float sacc = bfc[c];
#pragma unroll
    for (int k = 0; k < 32; k++) {
        const float4 a = *(const float4*)(hr + k * 4);
        const float4 wv = __ldg((const float4*)(wr + k * 4));
        sacc += a.x * wv.x + a.y * wv.y + a.z * wv.z + a.w * wv.w;
    }
    out[idx] = sacc;
}

#define SMEM_G1 ((256 * 33 + 512 * 17) * 4)
#define SMEM_G2 ((512 * 33 + 128 * 17) * 4)

extern "C" void kernel_launch(void* const* d_in, const int* in_sizes, int n_in,
                              void* d_out, int out_size) {
    const float* x      = (const float*)d_in[0];
    const int*   lens   = (const int*)d_in[1];
    const int*   ei     = (const int*)d_in[2];
    const float* Wih_f  = (const float*)d_in[3];
    const float* Whh_f  = (const float*)d_in[4];
    const float* b_f    = (const float*)d_in[5];
    const float* Wih_b  = (const float*)d_in[6];
    const float* Whh_b  = (const float*)d_in[7];
    const float* b_b    = (const float*)d_in[8];
    const float* W1     = (const float*)d_in[9];
    const float* a1s    = (const float*)d_in[10];
    const float* a1d    = (const float*)d_in[11];
    const float* bias1  = (const float*)d_in[12];
    const float* W2     = (const float*)d_in[13];
    const float* a2s    = (const float*)d_in[14];
    const float* a2d    = (const float*)d_in[15];
    const float* bias2  = (const float*)d_in[16];
    const float* Wfc    = (const float*)d_in[17];
    const float* bfc    = (const float*)d_in[18];
    float* out = (float*)d_out;

    float *p_hcat, *p_xh1, *p_al1s, *p_al1d, *p_agg1, *p_xh2, *p_al2s, *p_al2d, *p_agg2;
    cudaGetSymbolAddress((void**)&p_hcat, g_hcat);
    cudaGetSymbolAddress((void**)&p_xh1,  g_xh1);
    cudaGetSymbolAddress((void**)&p_al1s, g_al1s);
    cudaGetSymbolAddress((void**)&p_al1d, g_al1d);
    cudaGetSymbolAddress((void**)&p_agg1, g_agg1);
    cudaGetSymbolAddress((void**)&p_xh2,  g_xh2);
    cudaGetSymbolAddress((void**)&p_al2s, g_al2s);
    cudaGetSymbolAddress((void**)&p_al2d, g_al2d);
    cudaGetSymbolAddress((void**)&p_agg2, g_agg2);

    cudaFuncSetAttribute(lstm_kernel, cudaFuncAttributeMaxDynamicSharedMemorySize, LSTM_SMEM);
    cudaFuncSetAttribute(sgemm32_kernel<512, 256>, cudaFuncAttributeMaxDynamicSharedMemorySize, SMEM_G1);
    cudaFuncSetAttribute(sgemm32_kernel<128, 512>, cudaFuncAttributeMaxDynamicSharedMemorySize, SMEM_G2);

    zero_scratch<<<1024, 256>>>();
    lstm_kernel<<<dim3(625, 2), 256, LSTM_SMEM>>>(x, lens, Wih_f, Whh_f, b_f, Wih_b, Whh_b, b_b);

    // GAT layer 1
    sgemm32_kernel<512, 256><<<625, 256, SMEM_G1>>>(p_hcat, W1, p_xh1);
    gat_al<4><<<NN * 4 / 8, 256>>>(p_xh1, a1s, a1d, p_al1s, p_al1d);
    edge_b4<<<(EN + 255) / 256, 256>>>(ei);
    edge_c4<<<EN * 4 / 8, 256>>>(ei);
    bias_relu<<<(NN * 512 + 255) / 256, 256>>>(p_agg1, bias1, NN * 512, 511);

    // GAT layer 2
    sgemm32_kernel<128, 512><<<625, 256, SMEM_G2>>>(p_agg1, W2, p_xh2);
    gat_al<1><<<NN / 8, 256>>>(p_xh2, a2s, a2d, p_al2s, p_al2d);
    edge_b1<<<(EN + 255) / 256, 256>>>(ei);
    edge_c1<<<(EN + 7) / 8, 256>>>(ei);
    bias_relu<<<(NN * 128 + 255) / 256, 256>>>(p_agg2, bias2, NN * 128, 127);

    // FC head
    fc_kernel<<<(NN * NCLS + 255) / 256, 256>>>(Wfc, bfc, out);
}

// round 6
// speedup vs baseline: 2.4865x; 2.4865x over previous
#include <cuda_runtime.h>
#include <math.h>
#include <stdint.h>

#define NN 20000
#define TT 20
#define FF 128
#define HH 128
#define GHD 128
#define NHEADS 4
#define NCLS 10
#define EE 640000
#define EN (EE + NN)

// ---------------- scratch (device globals: allocation-free rule) ----------------
__device__ float g_hcat[NN * 256];
__device__ float g_xh1[NN * 512];
__device__ float g_al1s[NN * 4];
__device__ float g_al1d[NN * 4];
__device__ float g_ee1[EN * 4];
__device__ float g_den1[NN * 4];
__device__ float g_agg1[NN * 512];
__device__ float g_xh2[NN * 128];
__device__ float g_al2s[NN];
__device__ float g_al2d[NN];
__device__ float g_ee2[EN];
__device__ float g_den2[NN];
__device__ float g_agg2[NN * 128];
// tf32-rounded weights, layout [dir][k=256][gatecol=512]
__device__ float g_Wt[2 * 256 * 512];

__device__ __forceinline__ float lrelu(float x) { return x > 0.0f ? x : 0.2f * x; }
__device__ __forceinline__ void red_add_v4(float* p, float a, float b, float c, float d) {
    asm volatile("red.global.add.v4.f32 [%0], {%1,%2,%3,%4};"
                 :: "l"(p), "f"(a), "f"(b), "f"(c), "f"(d) : "memory");
}
__device__ __forceinline__ float rna_tf32(float v) {
    float o; asm("cvt.rna.tf32.f32 %0, %1;" : "=f"(o) : "f"(v)); return o;
}
__device__ __forceinline__ float fsig(float x) { return __fdividef(1.0f, 1.0f + __expf(-x)); }
__device__ __forceinline__ float ftanh(float x) {
    return __fdividef(2.0f, 1.0f + __expf(-2.0f * x)) - 1.0f;
}
__device__ __forceinline__ uint32_t smem_u32(const void* p) {
    uint32_t a;
    asm("{ .reg .u64 t; cvta.to.shared.u64 t, %1; cvt.u32.u64 %0, t; }" : "=r"(a) : "l"(p));
    return a;
}
#define CP16(dst, src)    asm volatile("cp.async.cg.shared.global [%0], [%1], 16;" :: "r"(dst), "l"(src))
#define CP_COMMIT()       asm volatile("cp.async.commit_group;" ::: "memory")
#define CP_WAIT0()        asm volatile("cp.async.wait_group 0;" ::: "memory")

// m16n8k8 tf32 mma: D += A*B. A row-major, B col-major (k x n).
__device__ __forceinline__ void mma_tf32(float* d, uint32_t a0, uint32_t a1, uint32_t a2,
                                         uint32_t a3, uint32_t b0, uint32_t b1) {
    asm volatile("mma.sync.aligned.m16n8k8.row.col.f32.tf32.tf32.f32 "
                 "{%0,%1,%2,%3}, {%4,%5,%6,%7}, {%8,%9}, {%0,%1,%2,%3};"
                 : "+f"(d[0]), "+f"(d[1]), "+f"(d[2]), "+f"(d[3])
                 : "r"(a0), "r"(a1), "r"(a2), "r"(a3), "r"(b0), "r"(b1));
}

// ---------------- zero the accumulated buffers ----------------
__global__ void zero_scratch() {
    const int stride = gridDim.x * blockDim.x;
    const int t0 = blockIdx.x * blockDim.x + threadIdx.x;
    for (int i = t0; i < NN * 512; i += stride) g_agg1[i] = 0.0f;
    for (int i = t0; i < NN * 128; i += stride) g_agg2[i] = 0.0f;
    for (int i = t0; i < NN * 4;   i += stride) g_den1[i] = 0.0f;
    for (int i = t0; i < NN;       i += stride) g_den2[i] = 0.0f;
}

// ---------------- weight prep: tf32-round into [dir][k][gatecol] ----------------
__global__ void prep_w(const float* __restrict__ Wih_f, const float* __restrict__ Whh_f,
                       const float* __restrict__ Wih_b, const float* __restrict__ Whh_b) {
    const int idx = blockIdx.x * blockDim.x + threadIdx.x;
    if (idx >= 2 * 256 * 512) return;
    const int dir = idx >> 17;
    const int rem = idx & 131071;
    const int k = rem >> 9;       // 0..255 (0-127: x, 128-255: h)
    const int c = rem & 511;      // gate col (torch i,f,g,o order)
    const float* Ws = dir ? (k < 128 ? Wih_b : Whh_b) : (k < 128 ? Wih_f : Whh_f);
    g_Wt[idx] = rna_tf32(Ws[(size_t)c * 128 + (k & 127)]);
}

// ---------------- tensor-core BiLSTM via mma.sync tf32 ----------------
// 64 seqs/CTA, 512 threads (16 warps). Per step: gates[64x512] = A[64x256] @ B[256x512].
// Warp (m = wid>>2, q = wid&3): rows m*16..+15, hidden cols q*32..+31, all 4 gates.
// Gate blocks share fragment layout -> cell math register-local.
// A smem: [64][260] (x cols 0-127, h cols 128-255). B: K=32 chunks [32][520] x2 (cp.async).
#define SA 260
#define SB 520
#define BOFF 16640
#define BIASOFF 49920
#define LENOFF 50432
#define LSTM_SMEM (50496 * 4)

__global__ void __launch_bounds__(512, 1) lstm_mma(
    const float* __restrict__ x, const int* __restrict__ lengths,
    const float* __restrict__ b_f, const float* __restrict__ b_b)
{
    extern __shared__ float sm[];
    float* const A_s   = sm;
    float* const B_s   = sm + BOFF;
    float* const biasf = sm + BIASOFF;
    int*   const len_s = (int*)(sm + LENOFF);
    const uint32_t B_u = smem_u32(B_s);

    const int tid = threadIdx.x;
    const int wid = tid >> 5, lane = tid & 31;
    const int g = lane >> 2, ctg = lane & 3;
    const int dir = blockIdx.y;
    const int seq0 = blockIdx.x * 64;
    const float* __restrict__ bb = dir ? b_b : b_f;
    const float* __restrict__ Wt = g_Wt + (size_t)dir * 131072;

    const int r0 = (wid >> 2) * 16;   // row group base
    const int q  = wid & 3;           // hidden col quarter
    const int rA = r0 + g, rB = r0 + g + 8;

    if (tid < 512) biasf[tid] = bb[tid];
    if (tid < 64) len_s[tid] = lengths[min(seq0 + tid, NN - 1)];
    for (int i = tid; i < 64 * 128; i += 512)           // zero h region
        A_s[(i >> 7) * SA + 128 + (i & 127)] = 0.0f;
    __syncthreads();

    const int lenA = len_s[rA], lenB = len_s[rB];

    float acc[4][4][4];   // [gate][ntile][frag]
    float cst[4][4];      // c state, same (ntile, frag pos) mapping
#pragma unroll
    for (int ni = 0; ni < 4; ni++)
#pragma unroll
        for (int p = 0; p < 4; p++) cst[ni][p] = 0.0f;

    for (int t = 0; t < TT; t++) {
        // ---- stage x_t (tf32-rounded) into A cols 0..127 ----
#pragma unroll
        for (int j = 0; j < 4; j++) {
            const int idx = j * 512 + tid;
            const int row = idx >> 5, f4 = idx & 31;
            const int ls = len_s[row];
            const int ttv = dir ? max(ls - 1 - t, 0) : t;
            const int sq = min(seq0 + row, NN - 1);
            const float4 v = *(const float4*)(x + ((size_t)sq * TT + ttv) * FF + f4 * 4);
            float4 r;
            r.x = rna_tf32(v.x); r.y = rna_tf32(v.y);
            r.z = rna_tf32(v.z); r.w = rna_tf32(v.w);
            *(float4*)(A_s + row * SA + f4 * 4) = r;
        }
#pragma unroll
        for (int gi = 0; gi < 4; gi++)
#pragma unroll
            for (int ni = 0; ni < 4; ni++)
#pragma unroll
                for (int p = 0; p < 4; p++) acc[gi][ni][p] = 0.0f;

        // ---- prefetch B chunk 0 ----
#pragma unroll
        for (int j = 0; j < 8; j++) {
            const int idx = j * 512 + tid;
            const int row = idx >> 7, f4 = idx & 127;
            CP16(B_u + (row * SB + f4 * 4) * 4, Wt + row * 512 + f4 * 4);
        }
        CP_COMMIT();

        for (int kc = 0; kc < 8; kc++) {
            CP_WAIT0();
            __syncthreads();   // chunk kc visible; all warps done with other buffer
            if (kc < 7) {
                const int nb = (kc + 1) & 1;
                const float* src = Wt + (kc + 1) * 16384;
#pragma unroll
                for (int j = 0; j < 8; j++) {
                    const int idx = j * 512 + tid;
                    const int row = idx >> 7, f4 = idx & 127;
                    CP16(B_u + (nb * BOFF + row * SB + f4 * 4) * 4, src + row * 512 + f4 * 4);
                }
                CP_COMMIT();
            }
            // ---- compute chunk kc ----
            const float* Bb = B_s + (kc & 1) * BOFF;
#pragma unroll
            for (int ks = 0; ks < 4; ks++) {
                const int k = kc * 32 + ks * 8;
                const uint32_t a0 = __float_as_uint(A_s[rA * SA + k + ctg]);
                const uint32_t a1 = __float_as_uint(A_s[rB * SA + k + ctg]);
                const uint32_t a2 = __float_as_uint(A_s[rA * SA + k + ctg + 4]);
                const uint32_t a3 = __float_as_uint(A_s[rB * SA + k + ctg + 4]);
                const float* B0 = Bb + (ks * 8 + ctg) * SB + g;
                const float* B4 = B0 + 4 * SB;
#pragma unroll
                for (int gi = 0; gi < 4; gi++) {
#pragma unroll
                    for (int ni = 0; ni < 4; ni++) {
                        const int n0 = gi * 128 + q * 32 + ni * 8;
                        const uint32_t b0 = __float_as_uint(B0[n0]);
                        const uint32_t b1 = __float_as_uint(B4[n0]);
                        mma_tf32(acc[gi][ni], a0, a1, a2, a3, b0, b1);
                    }
                }
            }
        }

        __syncthreads();   // all mma reads of A_s h-region done before h writeback

        // ---- epilogue: cell math (register-local), h writeback ----
#pragma unroll
        for (int ni = 0; ni < 4; ni++) {
            const int hc0 = q * 32 + ni * 8 + 2 * ctg;
#pragma unroll
            for (int p = 0; p < 4; p++) {
                const int col = hc0 + (p & 1);
                const int row = (p < 2) ? rA : rB;
                const bool act = t < ((p < 2) ? lenA : lenB);
                const float pi = acc[0][ni][p] + biasf[col];
                const float pf = acc[1][ni][p] + biasf[128 + col];
                const float pg = acc[2][ni][p] + biasf[256 + col];
                const float po = acc[3][ni][p] + biasf[384 + col];
                const float cn = fsig(pf) * cst[ni][p] + fsig(pi) * ftanh(pg);
                const float hn = fsig(po) * ftanh(cn);
                if (act) {
                    cst[ni][p] = cn;
                    A_s[row * SA + 128 + col] = rna_tf32(hn);
                }
            }
        }
        __syncthreads();   // h visible before next step (or final copy)
    }

    // ---- final frozen h -> g_hcat ----
    for (int i = tid; i < 64 * 32; i += 512) {
        const int row = i >> 5, f4 = i & 31;
        const int seq = seq0 + row;
        if (seq < NN) {
            const float4 v = *(const float4*)(A_s + row * SA + 128 + f4 * 4);
            *(float4*)(g_hcat + (size_t)seq * 256 + dir * 128 + f4 * 4) = v;
        }
    }
}

// ---------------- generic 32-row SGEMM: C[N][COLS] = A[N][KTOT] @ W[COLS][KTOT]^T ----------------
template <int COLS, int KTOT>
__global__ void __launch_bounds__(256, 2) sgemm32_kernel(
    const float* __restrict__ A, const float* __restrict__ W, float* __restrict__ C)
{
    constexpr int TN = COLS / 64;
    extern __shared__ float sm[];
    float* A_s = sm;              // [KTOT][33]
    float* B_s = sm + KTOT * 33;  // [COLS][17]
    const int tid = threadIdx.x;
    const int tr = tid >> 6, tc = tid & 63;
    const int row0 = blockIdx.x * 32;

    constexpr int K4 = KTOT / 4;
    for (int idx = tid; idx < 32 * K4; idx += 256) {
        const int r = idx / K4, k4 = idx % K4;
        const float4 v = *(const float4*)(A + (size_t)(row0 + r) * KTOT + k4 * 4);
        A_s[(k4 * 4 + 0) * 33 + r] = v.x;
        A_s[(k4 * 4 + 1) * 33 + r] = v.y;
        A_s[(k4 * 4 + 2) * 33 + r] = v.z;
        A_s[(k4 * 4 + 3) * 33 + r] = v.w;
    }
    float acc[8][TN];
#pragma unroll
    for (int i = 0; i < 8; i++)
#pragma unroll
        for (int j = 0; j < TN; j++) acc[i][j] = 0.0f;

    for (int kc = 0; kc < KTOT / 16; kc++) {
        const int k0 = kc * 16;
        const int qq = tid & 3, cb = tid >> 2;
#pragma unroll
        for (int cc = 0; cc < COLS / 64; cc++) {
            const int c = cb + 64 * cc;
            const float4 w4 = *(const float4*)(W + (size_t)c * KTOT + k0 + qq * 4);
            B_s[c * 17 + qq * 4 + 0] = w4.x;
            B_s[c * 17 + qq * 4 + 1] = w4.y;
            B_s[c * 17 + qq * 4 + 2] = w4.z;
            B_s[c * 17 + qq * 4 + 3] = w4.w;
        }
        __syncthreads();
#pragma unroll
        for (int kk = 0; kk < 16; kk++) {
            float av[8], bv[TN];
#pragma unroll
            for (int i = 0; i < 8; i++) av[i] = A_s[(k0 + kk) * 33 + tr * 8 + i];
#pragma unroll
            for (int j = 0; j < TN; j++) bv[j] = B_s[(tc + 64 * j) * 17 + kk];
#pragma unroll
            for (int i = 0; i < 8; i++)
#pragma unroll
                for (int j = 0; j < TN; j++) acc[i][j] = fmaf(av[i], bv[j], acc[i][j]);
        }
        __syncthreads();
    }
#pragma unroll
    for (int i = 0; i < 8; i++)
#pragma unroll
        for (int j = 0; j < TN; j++)
            C[(size_t)(row0 + tr * 8 + i) * COLS + tc + 64 * j] = acc[i][j];
}

// ---------------- GAT attention-logit projections (warp per (node, head)) ----------------
template <int NH>
__global__ void gat_al(const float* __restrict__ xh, const float* __restrict__ asrc,
                       const float* __restrict__ adst, float* __restrict__ als,
                       float* __restrict__ ald)
{
    const int w = (blockIdx.x * blockDim.x + threadIdx.x) >> 5;
    const int lane = threadIdx.x & 31;
    if (w >= NN * NH) return;
    const int n = w / NH, h = w % NH;
    const float4 v  = *(const float4*)(xh + (size_t)n * (NH * GHD) + h * GHD + lane * 4);
    const float4 s4 = *(const float4*)(asrc + h * GHD + lane * 4);
    const float4 d4 = *(const float4*)(adst + h * GHD + lane * 4);
    float s = v.x * s4.x + v.y * s4.y + v.z * s4.z + v.w * s4.w;
    float d = v.x * d4.x + v.y * d4.y + v.z * d4.z + v.w * d4.w;
#pragma unroll
    for (int o = 16; o > 0; o >>= 1) {
        s += __shfl_xor_sync(0xffffffffu, s, o);
        d += __shfl_xor_sync(0xffffffffu, d, o);
    }
    if (lane == 0) { als[w] = s; ald[w] = d; }
}

// ---------------- edge softmax numerator + denominator (layer 1, 4 heads) ----------------
__global__ void edge_b4(const int* __restrict__ ei) {
    const int e = blockIdx.x * blockDim.x + threadIdx.x;
    if (e >= EN) return;
    int s, d;
    if (e < EE) { s = ei[e]; d = ei[EE + e]; } else { s = d = e - EE; }
    const float4 as = *(const float4*)(g_al1s + (size_t)s * 4);
    const float4 ad = *(const float4*)(g_al1d + (size_t)d * 4);
    float4 ev;
    ev.x = expf(lrelu(as.x + ad.x));
    ev.y = expf(lrelu(as.y + ad.y));
    ev.z = expf(lrelu(as.z + ad.z));
    ev.w = expf(lrelu(as.w + ad.w));
    *(float4*)(g_ee1 + (size_t)e * 4) = ev;
    red_add_v4(g_den1 + (size_t)d * 4, ev.x, ev.y, ev.z, ev.w);
}

// ---------------- weighted aggregate (layer 1): warp per (edge, head) ----------------
__global__ void edge_c4(const int* __restrict__ ei) {
    const int w = (blockIdx.x * blockDim.x + threadIdx.x) >> 5;
    const int lane = threadIdx.x & 31;
    if (w >= EN * NHEADS) return;
    const int e = w >> 2, h = w & 3;
    int s, d;
    if (e < EE) { s = ei[e]; d = ei[EE + e]; } else { s = d = e - EE; }
    const float alpha = g_ee1[(size_t)e * 4 + h] / (g_den1[(size_t)d * 4 + h] + 1e-16f);
    const float4 v = *(const float4*)(g_xh1 + (size_t)s * 512 + h * GHD + lane * 4);
    red_add_v4(g_agg1 + (size_t)d * 512 + h * GHD + lane * 4,
               v.x * alpha, v.y * alpha, v.z * alpha, v.w * alpha);
}

// ---------------- layer 2 (1 head) ----------------
__global__ void edge_b1(const int* __restrict__ ei) {
    const int e = blockIdx.x * blockDim.x + threadIdx.x;
    if (e >= EN) return;
    int s, d;
    if (e < EE) { s = ei[e]; d = ei[EE + e]; } else { s = d = e - EE; }
    const float ev = expf(lrelu(g_al2s[s] + g_al2d[d]));
    g_ee2[e] = ev;
    atomicAdd(g_den2 + d, ev);
}

__global__ void edge_c1(const int* __restrict__ ei) {
    const int w = (blockIdx.x * blockDim.x + threadIdx.x) >> 5;
    const int lane = threadIdx.x & 31;
    if (w >= EN) return;
    int s, d;
    if (w < EE) { s = ei[w]; d = ei[EE + w]; } else { s = d = w - EE; }
    const float alpha = g_ee2[w] / (g_den2[d] + 1e-16f);
    const float4 v = *(const float4*)(g_xh2 + (size_t)s * 128 + lane * 4);
    red_add_v4(g_agg2 + (size_t)d * 128 + lane * 4,
               v.x * alpha, v.y * alpha, v.z * alpha, v.w * alpha);
}

// ---------------- bias + relu (in place) ----------------
__global__ void bias_relu(float* __restrict__ buf, const float* __restrict__ bias,
                          int total, int colmask) {
    const int i = blockIdx.x * blockDim.x + threadIdx.x;
    if (i >= total) return;
    buf[i] = fmaxf(buf[i] + bias[i & colmask], 0.0f);
}

// ---------------- final FC ----------------
__global__ void fc_kernel(const float* __restrict__ Wfc, const float* __restrict__ bfc,
                          float* __restrict__ out) {
    const int idx = blockIdx.x * blockDim.x + threadIdx.x;
    if (idx >= NN * NCLS) return;
    const int n = idx / NCLS, c = idx - n * NCLS;
    const float* hr = g_agg2 + (size_t)n * 128;
    const float* wr = Wfc + c * 128;
    float sacc = bfc[c];
#pragma unroll
    for (int k = 0; k < 32; k++) {
        const float4 a = *(const float4*)(hr + k * 4);
        const float4 wv = __ldg((const float4*)(wr + k * 4));
        sacc += a.x * wv.x + a.y * wv.y + a.z * wv.z + a.w * wv.w;
    }
    out[idx] = sacc;
}

#define SMEM_G1 ((256 * 33 + 512 * 17) * 4)
#define SMEM_G2 ((512 * 33 + 128 * 17) * 4)

extern "C" void kernel_launch(void* const* d_in, const int* in_sizes, int n_in,
                              void* d_out, int out_size) {
    const float* x      = (const float*)d_in[0];
    const int*   lens   = (const int*)d_in[1];
    const int*   ei     = (const int*)d_in[2];
    const float* Wih_f  = (const float*)d_in[3];
    const float* Whh_f  = (const float*)d_in[4];
    const float* b_f    = (const float*)d_in[5];
    const float* Wih_b  = (const float*)d_in[6];
    const float* Whh_b  = (const float*)d_in[7];
    const float* b_b    = (const float*)d_in[8];
    const float* W1     = (const float*)d_in[9];
    const float* a1s    = (const float*)d_in[10];
    const float* a1d    = (const float*)d_in[11];
    const float* bias1  = (const float*)d_in[12];
    const float* W2     = (const float*)d_in[13];
    const float* a2s    = (const float*)d_in[14];
    const float* a2d    = (const float*)d_in[15];
    const float* bias2  = (const float*)d_in[16];
    const float* Wfc    = (const float*)d_in[17];
    const float* bfc    = (const float*)d_in[18];
    float* out = (float*)d_out;

    float *p_hcat, *p_xh1, *p_al1s, *p_al1d, *p_agg1, *p_xh2, *p_al2s, *p_al2d, *p_agg2;
    cudaGetSymbolAddress((void**)&p_hcat, g_hcat);
    cudaGetSymbolAddress((void**)&p_xh1,  g_xh1);
    cudaGetSymbolAddress((void**)&p_al1s, g_al1s);
    cudaGetSymbolAddress((void**)&p_al1d, g_al1d);
    cudaGetSymbolAddress((void**)&p_agg1, g_agg1);
    cudaGetSymbolAddress((void**)&p_xh2,  g_xh2);
    cudaGetSymbolAddress((void**)&p_al2s, g_al2s);
    cudaGetSymbolAddress((void**)&p_al2d, g_al2d);
    cudaGetSymbolAddress((void**)&p_agg2, g_agg2);

    cudaFuncSetAttribute(lstm_mma, cudaFuncAttributeMaxDynamicSharedMemorySize, LSTM_SMEM);
    cudaFuncSetAttribute(sgemm32_kernel<512, 256>, cudaFuncAttributeMaxDynamicSharedMemorySize, SMEM_G1);
    cudaFuncSetAttribute(sgemm32_kernel<128, 512>, cudaFuncAttributeMaxDynamicSharedMemorySize, SMEM_G2);

    zero_scratch<<<1024, 256>>>();
    prep_w<<<1024, 256>>>(Wih_f, Whh_f, Wih_b, Whh_b);
    lstm_mma<<<dim3(313, 2), 512, LSTM_SMEM>>>(x, lens, b_f, b_b);

    // GAT layer 1
    sgemm32_kernel<512, 256><<<625, 256, SMEM_G1>>>(p_hcat, W1, p_xh1);
    gat_al<4><<<NN * 4 / 8, 256>>>(p_xh1, a1s, a1d, p_al1s, p_al1d);
    edge_b4<<<(EN + 255) / 256, 256>>>(ei);
    edge_c4<<<EN * 4 / 8, 256>>>(ei);
    bias_relu<<<(NN * 512 + 255) / 256, 256>>>(p_agg1, bias1, NN * 512, 511);

    // GAT layer 2
    sgemm32_kernel<128, 512><<<625, 256, SMEM_G2>>>(p_agg1, W2, p_xh2);
    gat_al<1><<<NN / 8, 256>>>(p_xh2, a2s, a2d, p_al2s, p_al2d);
    edge_b1<<<(EN + 255) / 256, 256>>>(ei);
    edge_c1<<<(EN + 7) / 8, 256>>>(ei);
    bias_relu<<<(NN * 128 + 255) / 256, 256>>>(p_agg2, bias2, NN * 128, 127);

    // FC head
    fc_kernel<<<(NN * NCLS + 255) / 256, 256>>>(Wfc, bfc, out);
}

// round 8
// speedup vs baseline: 3.0439x; 1.2242x over previous
#include <cuda_runtime.h>
#include <math.h>
#include <stdint.h>

#define NN 20000
#define TT 20
#define FF 128
#define HH 128
#define GHD 128
#define NHEADS 4
#define NCLS 10
#define EE 640000
#define EN (EE + NN)

// ---------------- scratch (device globals: allocation-free rule) ----------------
__device__ float g_hcat[NN * 256];
__device__ float g_xh1[NN * 512];
__device__ float g_al1s[NN * 4];
__device__ float g_al1d[NN * 4];
__device__ float g_agg1[NN * 512];
__device__ float g_xh2[NN * 128];
__device__ float g_al2s[NN];
__device__ float g_al2d[NN];
// LSTM weights tf32-rounded: [dir][k=256][gatecol=512]
__device__ float g_Wt[2 * 256 * 512];
// GAT weights tf32-rounded, [k][col]
__device__ float g_W1t[256 * 512];
__device__ float g_W2t[512 * 128];
// CSR by dst
__device__ int g_cnt[NN];
__device__ int g_base[NN + 1];
__device__ int g_srcs[EN];

__device__ __forceinline__ float lrelu(float x) { return x > 0.0f ? x : 0.2f * x; }
__device__ __forceinline__ float rna_tf32(float v) {
    float o; asm("cvt.rna.tf32.f32 %0, %1;" : "=f"(o) : "f"(v)); return o;
}
__device__ __forceinline__ float fsig(float x) { return __fdividef(1.0f, 1.0f + __expf(-x)); }
__device__ __forceinline__ float ftanh(float x) {
    return __fdividef(2.0f, 1.0f + __expf(-2.0f * x)) - 1.0f;
}
__device__ __forceinline__ uint32_t smem_u32(const void* p) {
    uint32_t a;
    asm("{ .reg .u64 t; cvta.to.shared.u64 t, %1; cvt.u32.u64 %0, t; }" : "=r"(a) : "l"(p));
    return a;
}
#define CP16(dst, src)    asm volatile("cp.async.cg.shared.global [%0], [%1], 16;" :: "r"(dst), "l"(src))
#define CP_COMMIT()       asm volatile("cp.async.commit_group;" ::: "memory")
#define CP_WAIT0()        asm volatile("cp.async.wait_group 0;" ::: "memory")

// m16n8k8 tf32 mma: D += A*B. A row-major, B col-major (k x n).
__device__ __forceinline__ void mma_tf32(float* d, uint32_t a0, uint32_t a1, uint32_t a2,
                                         uint32_t a3, uint32_t b0, uint32_t b1) {
    asm volatile("mma.sync.aligned.m16n8k8.row.col.f32.tf32.tf32.f32 "
                 "{%0,%1,%2,%3}, {%4,%5,%6,%7}, {%8,%9}, {%0,%1,%2,%3};"
                 : "+f"(d[0]), "+f"(d[1]), "+f"(d[2]), "+f"(d[3])
                 : "r"(a0), "r"(a1), "r"(a2), "r"(a3), "r"(b0), "r"(b1));
}

// ---------------- weight prep ----------------
__global__ void prep_w(const float* __restrict__ Wih_f, const float* __restrict__ Whh_f,
                       const float* __restrict__ Wih_b, const float* __restrict__ Whh_b) {
    const int idx = blockIdx.x * blockDim.x + threadIdx.x;
    if (idx >= 2 * 256 * 512) return;
    const int dir = idx >> 17;
    const int rem = idx & 131071;
    const int k = rem >> 9;
    const int c = rem & 511;
    const float* Ws = dir ? (k < 128 ? Wih_b : Whh_b) : (k < 128 ? Wih_f : Whh_f);
    g_Wt[idx] = rna_tf32(Ws[(size_t)c * 128 + (k & 127)]);
}
__global__ void prep_gw(const float* __restrict__ W1, const float* __restrict__ W2) {
    const int idx = blockIdx.x * blockDim.x + threadIdx.x;
    if (idx < 256 * 512) {
        const int k = idx >> 9, c = idx & 511;
        g_W1t[idx] = rna_tf32(W1[(size_t)c * 256 + k]);
    }
    const int j = idx - 256 * 512;
    if (j >= 0 && j < 512 * 128) {
        const int k = j >> 7, c = j & 127;
        g_W2t[j] = rna_tf32(W2[(size_t)c * 512 + k]);
    }
}

// ---------------- CSR build (edges + self loops, grouped by dst) ----------------
__global__ void csr_zero() {
    const int i = blockIdx.x * blockDim.x + threadIdx.x;
    if (i < NN) g_cnt[i] = 0;
}
__global__ void csr_hist(const int* __restrict__ ei) {
    const int e = blockIdx.x * blockDim.x + threadIdx.x;
    if (e >= EN) return;
    const int d = (e < EE) ? ei[EE + e] : (e - EE);
    atomicAdd(&g_cnt[d], 1);
}
__global__ void __launch_bounds__(1024, 1) csr_scan() {
    __shared__ int ps[1024];
    const int tid = threadIdx.x;
    const int base = tid * 20;
    int local[20];
    int s = 0;
#pragma unroll
    for (int i = 0; i < 20; i++) {
        const int idx = base + i;
        const int c = (idx < NN) ? g_cnt[idx] : 0;
        local[i] = s;
        s += c;
    }
    ps[tid] = s;
    __syncthreads();
    for (int off = 1; off < 1024; off <<= 1) {
        int v = (tid >= off) ? ps[tid - off] : 0;
        __syncthreads();
        ps[tid] += v;
        __syncthreads();
    }
    const int excl = (tid == 0) ? 0 : ps[tid - 1];
#pragma unroll
    for (int i = 0; i < 20; i++) {
        const int idx = base + i;
        if (idx < NN) g_base[idx] = excl + local[i];
    }
    if (tid == 1023) g_base[NN] = ps[1023];
    __syncthreads();
    for (int i = tid; i < NN; i += 1024) g_cnt[i] = g_base[i];  // cursor
}
__global__ void csr_scatter(const int* __restrict__ ei) {
    const int e = blockIdx.x * blockDim.x + threadIdx.x;
    if (e >= EN) return;
    int s, d;
    if (e < EE) { s = ei[e]; d = ei[EE + e]; } else { s = d = e - EE; }
    const int pos = atomicAdd(&g_cnt[d], 1);
    g_srcs[pos] = s;
}

// ---------------- tensor-core BiLSTM via mma.sync tf32 (unchanged from R6) ----------------
#define SA 260
#define SB 520
#define BOFF 16640
#define BIASOFF 49920
#define LENOFF 50432
#define LSTM_SMEM (50496 * 4)

__global__ void __launch_bounds__(512, 1) lstm_mma(
    const float* __restrict__ x, const int* __restrict__ lengths,
    const float* __restrict__ b_f, const float* __restrict__ b_b)
{
    extern __shared__ float sm[];
    float* const A_s   = sm;
    float* const B_s   = sm + BOFF;
    float* const biasf = sm + BIASOFF;
    int*   const len_s = (int*)(sm + LENOFF);
    const uint32_t B_u = smem_u32(B_s);

    const int tid = threadIdx.x;
    const int wid = tid >> 5, lane = tid & 31;
    const int g = lane >> 2, ctg = lane & 3;
    const int dir = blockIdx.y;
    const int seq0 = blockIdx.x * 64;
    const float* __restrict__ bb = dir ? b_b : b_f;
    const float* __restrict__ Wt = g_Wt + (size_t)dir * 131072;

    const int r0 = (wid >> 2) * 16;
    const int q  = wid & 3;
    const int rA = r0 + g, rB = r0 + g + 8;

    if (tid < 512) biasf[tid] = bb[tid];
    if (tid < 64) len_s[tid] = lengths[min(seq0 + tid, NN - 1)];
    for (int i = tid; i < 64 * 128; i += 512)
        A_s[(i >> 7) * SA + 128 + (i & 127)] = 0.0f;
    __syncthreads();

    const int lenA = len_s[rA], lenB = len_s[rB];

    float acc[4][4][4];
    float cst[4][4];
#pragma unroll
    for (int ni = 0; ni < 4; ni++)
#pragma unroll
        for (int p = 0; p < 4; p++) cst[ni][p] = 0.0f;

    for (int t = 0; t < TT; t++) {
#pragma unroll
        for (int j = 0; j < 4; j++) {
            const int idx = j * 512 + tid;
            const int row = idx >> 5, f4 = idx & 31;
            const int ls = len_s[row];
            const int ttv = dir ? max(ls - 1 - t, 0) : t;
            const int sq = min(seq0 + row, NN - 1);
            const float4 v = *(const float4*)(x + ((size_t)sq * TT + ttv) * FF + f4 * 4);
            float4 r;
            r.x = rna_tf32(v.x); r.y = rna_tf32(v.y);
            r.z = rna_tf32(v.z); r.w = rna_tf32(v.w);
            *(float4*)(A_s + row * SA + f4 * 4) = r;
        }
#pragma unroll
        for (int gi = 0; gi < 4; gi++)
#pragma unroll
            for (int ni = 0; ni < 4; ni++)
#pragma unroll
                for (int p = 0; p < 4; p++) acc[gi][ni][p] = 0.0f;

#pragma unroll
        for (int j = 0; j < 8; j++) {
            const int idx = j * 512 + tid;
            const int row = idx >> 7, f4 = idx & 127;
            CP16(B_u + (row * SB + f4 * 4) * 4, Wt + row * 512 + f4 * 4);
        }
        CP_COMMIT();

        for (int kc = 0; kc < 8; kc++) {
            CP_WAIT0();
            __syncthreads();
            if (kc < 7) {
                const int nb = (kc + 1) & 1;
                const float* src = Wt + (kc + 1) * 16384;
#pragma unroll
                for (int j = 0; j < 8; j++) {
                    const int idx = j * 512 + tid;
                    const int row = idx >> 7, f4 = idx & 127;
                    CP16(B_u + (nb * BOFF + row * SB + f4 * 4) * 4, src + row * 512 + f4 * 4);
                }
                CP_COMMIT();
            }
            const float* Bb = B_s + (kc & 1) * BOFF;
#pragma unroll
            for (int ks = 0; ks < 4; ks++) {
                const int k = kc * 32 + ks * 8;
                const uint32_t a0 = __float_as_uint(A_s[rA * SA + k + ctg]);
                const uint32_t a1 = __float_as_uint(A_s[rB * SA + k + ctg]);
                const uint32_t a2 = __float_as_uint(A_s[rA * SA + k + ctg + 4]);
                const uint32_t a3 = __float_as_uint(A_s[rB * SA + k + ctg + 4]);
                const float* B0 = Bb + (ks * 8 + ctg) * SB + g;
                const float* B4 = B0 + 4 * SB;
#pragma unroll
                for (int gi = 0; gi < 4; gi++) {
#pragma unroll
                    for (int ni = 0; ni < 4; ni++) {
                        const int n0 = gi * 128 + q * 32 + ni * 8;
                        const uint32_t b0 = __float_as_uint(B0[n0]);
                        const uint32_t b1 = __float_as_uint(B4[n0]);
                        mma_tf32(acc[gi][ni], a0, a1, a2, a3, b0, b1);
                    }
                }
            }
        }

        __syncthreads();

#pragma unroll
        for (int ni = 0; ni < 4; ni++) {
            const int hc0 = q * 32 + ni * 8 + 2 * ctg;
#pragma unroll
            for (int p = 0; p < 4; p++) {
                const int col = hc0 + (p & 1);
                const int row = (p < 2) ? rA : rB;
                const bool act = t < ((p < 2) ? lenA : lenB);
                const float pi = acc[0][ni][p] + biasf[col];
                const float pf = acc[1][ni][p] + biasf[128 + col];
                const float pg = acc[2][ni][p] + biasf[256 + col];
                const float po = acc[3][ni][p] + biasf[384 + col];
                const float cn = fsig(pf) * cst[ni][p] + fsig(pi) * ftanh(pg);
                const float hn = fsig(po) * ftanh(cn);
                if (act) {
                    cst[ni][p] = cn;
                    A_s[row * SA + 128 + col] = rna_tf32(hn);
                }
            }
        }
        __syncthreads();
    }

    for (int i = tid; i < 64 * 32; i += 512) {
        const int row = i >> 5, f4 = i & 31;
        const int seq = seq0 + row;
        if (seq < NN) {
            const float4 v = *(const float4*)(A_s + row * SA + 128 + f4 * 4);
            *(float4*)(g_hcat + (size_t)seq * 256 + dir * 128 + f4 * 4) = v;
        }
    }
}

// ---------------- generic tensor GEMM: C[N][COLS] = A[N][KTOT] @ Bt[KTOT][COLS] ----------------
// 64 rows/CTA, 512 threads (16 warps). Same fragment layout as lstm_mma.
template <int KTOT, int COLS>
__global__ void __launch_bounds__(512, 1) gemm_mma(
    const float* __restrict__ A, const float* __restrict__ Bt, float* __restrict__ C)
{
    constexpr int SA2 = KTOT + 4;
    constexpr int SB2 = COLS + 8;
    constexpr int GI = COLS / 128;
    constexpr int BO2 = 32 * SB2;
    extern __shared__ float sm[];
    float* const A_s = sm;
    float* const B_s = sm + 64 * SA2;
    const uint32_t B_u = smem_u32(B_s);

    const int tid = threadIdx.x;
    const int wid = tid >> 5, lane = tid & 31;
    const int g = lane >> 2, ctg = lane & 3;
    const int r0 = (wid >> 2) * 16;
    const int q = wid & 3;
    const int rA = r0 + g, rB = r0 + g + 8;
    const int row0 = blockIdx.x * 64;

    constexpr int K4 = KTOT / 4;
    for (int idx = tid; idx < 64 * K4; idx += 512) {
        const int row = idx / K4, c4 = idx % K4;
        const int sq = min(row0 + row, NN - 1);
        const float4 v = *(const float4*)(A + (size_t)sq * KTOT + c4 * 4);
        float4 r;
        r.x = rna_tf32(v.x); r.y = rna_tf32(v.y);
        r.z = rna_tf32(v.z); r.w = rna_tf32(v.w);
        *(float4*)(A_s + row * SA2 + c4 * 4) = r;
    }

    float acc[GI][4][4];
#pragma unroll
    for (int gi = 0; gi < GI; gi++)
#pragma unroll
        for (int ni = 0; ni < 4; ni++)
#pragma unroll
            for (int p = 0; p < 4; p++) acc[gi][ni][p] = 0.0f;

    constexpr int NC = KTOT / 32;
    constexpr int C4 = COLS / 4;
    for (int j = tid; j < 8 * COLS; j += 512) {
        const int row = j / C4, c4 = j % C4;
        CP16(B_u + (row * SB2 + c4 * 4) * 4, Bt + (size_t)row * COLS + c4 * 4);
    }
    CP_COMMIT();

    for (int kc = 0; kc < NC; kc++) {
        CP_WAIT0();
        __syncthreads();
        if (kc < NC - 1) {
            const int nb = (kc + 1) & 1;
            const float* src = Bt + (size_t)(kc + 1) * 32 * COLS;
            for (int j = tid; j < 8 * COLS; j += 512) {
                const int row = j / C4, c4 = j % C4;
                CP16(B_u + (nb * BO2 + row * SB2 + c4 * 4) * 4, src + (size_t)row * COLS + c4 * 4);
            }
            CP_COMMIT();
        }
        const float* Bb = B_s + (kc & 1) * BO2;
#pragma unroll
        for (int ks = 0; ks < 4; ks++) {
            const int k = kc * 32 + ks * 8;
            const uint32_t a0 = __float_as_uint(A_s[rA * SA2 + k + ctg]);
            const uint32_t a1 = __float_as_uint(A_s[rB * SA2 + k + ctg]);
            const uint32_t a2 = __float_as_uint(A_s[rA * SA2 + k + ctg + 4]);
            const uint32_t a3 = __float_as_uint(A_s[rB * SA2 + k + ctg + 4]);
            const float* B0 = Bb + (ks * 8 + ctg) * SB2 + g;
            const float* B4 = B0 + 4 * SB2;
#pragma unroll
            for (int gi = 0; gi < GI; gi++) {
#pragma unroll
                for (int ni = 0; ni < 4; ni++) {
                    const int n0 = gi * 128 + q * 32 + ni * 8;
                    const uint32_t b0 = __float_as_uint(B0[n0]);
                    const uint32_t b1 = __float_as_uint(B4[n0]);
                    mma_tf32(acc[gi][ni], a0, a1, a2, a3, b0, b1);
                }
            }
        }
    }

#pragma unroll
    for (int gi = 0; gi < GI; gi++)
#pragma unroll
        for (int ni = 0; ni < 4; ni++) {
            const int n0 = gi * 128 + q * 32 + ni * 8 + 2 * ctg;
            if (row0 + rA < NN)
                *(float2*)(C + (size_t)(row0 + rA) * COLS + n0) =
                    make_float2(acc[gi][ni][0], acc[gi][ni][1]);
            if (row0 + rB < NN)
                *(float2*)(C + (size_t)(row0 + rB) * COLS + n0) =
                    make_float2(acc[gi][ni][2], acc[gi][ni][3]);
        }
}

// ---------------- GAT attention-logit projections (warp per (node, head)) ----------------
template <int NH>
__global__ void gat_al(const float* __restrict__ xh, const float* __restrict__ asrc,
                       const float* __restrict__ adst, float* __restrict__ als,
                       float* __restrict__ ald)
{
    const int w = (blockIdx.x * blockDim.x + threadIdx.x) >> 5;
    const int lane = threadIdx.x & 31;
    if (w >= NN * NH) return;
    const int n = w / NH, h = w % NH;
    const float4 v  = *(const float4*)(xh + (size_t)n * (NH * GHD) + h * GHD + lane * 4);
    const float4 s4 = *(const float4*)(asrc + h * GHD + lane * 4);
    const float4 d4 = *(const float4*)(adst + h * GHD + lane * 4);
    float s = v.x * s4.x + v.y * s4.y + v.z * s4.z + v.w * s4.w;
    float d = v.x * d4.x + v.y * d4.y + v.z * d4.z + v.w * d4.w;
#pragma unroll
    for (int o = 16; o > 0; o >>= 1) {
        s += __shfl_xor_sync(0xffffffffu, s, o);
        d += __shfl_xor_sync(0xffffffffu, d, o);
    }
    if (lane == 0) { als[w] = s; ald[w] = d; }
}

// ---------------- layer-1 gather: warp per (dst, head), CSR, no atomics ----------------
// out = relu( (sum_e ee*xh1[src]) / (sum_e ee + 1e-16) + bias1 )
__global__ void gat_gather4(const float* __restrict__ bias1) {
    const int w = (blockIdx.x * blockDim.x + threadIdx.x) >> 5;
    const int lane = threadIdx.x & 31;
    if (w >= NN * NHEADS) return;
    const int d = w >> 2, h = w & 3;
    const float aldv = g_al1d[d * 4 + h];
    const int beg = g_base[d], end = g_base[d + 1];
    float ax = 0.0f, ay = 0.0f, az = 0.0f, aw = 0.0f, den = 0.0f;
#pragma unroll 4
    for (int e = beg; e < end; e++) {
        const int s = g_srcs[e];
        const float ee = __expf(lrelu(g_al1s[s * 4 + h] + aldv));
        den += ee;
        const float4 v = *(const float4*)(g_xh1 + (size_t)s * 512 + h * GHD + lane * 4);
        ax += ee * v.x; ay += ee * v.y; az += ee * v.z; aw += ee * v.w;
    }
    const float inv = __fdividef(1.0f, den + 1e-16f);
    const float4 b = *(const float4*)(bias1 + h * GHD + lane * 4);
    float4 o;
    o.x = fmaxf(ax * inv + b.x, 0.0f);
    o.y = fmaxf(ay * inv + b.y, 0.0f);
    o.z = fmaxf(az * inv + b.z, 0.0f);
    o.w = fmaxf(aw * inv + b.w, 0.0f);
    *(float4*)(g_agg1 + (size_t)d * 512 + h * GHD + lane * 4) = o;
}

// ---------------- layer-2 gather + fused FC: warp per dst ----------------
__global__ void gat_gather1_fc(const float* __restrict__ bias2,
                               const float* __restrict__ Wfc, const float* __restrict__ bfc,
                               float* __restrict__ out) {
    const int w = (blockIdx.x * blockDim.x + threadIdx.x) >> 5;
    const int lane = threadIdx.x & 31;
    if (w >= NN) return;
    const int d = w;
    const float aldv = g_al2d[d];
    const int beg = g_base[d], end = g_base[d + 1];
    float ax = 0.0f, ay = 0.0f, az = 0.0f, aw = 0.0f, den = 0.0f;
#pragma unroll 4
    for (int e = beg; e < end; e++) {
        const int s = g_srcs[e];
        const float ee = __expf(lrelu(g_al2s[s] + aldv));
        den += ee;
        const float4 v = *(const float4*)(g_xh2 + (size_t)s * 128 + lane * 4);
        ax += ee * v.x; ay += ee * v.y; az += ee * v.z; aw += ee * v.w;
    }
    const float inv = __fdividef(1.0f, den + 1e-16f);
    const float4 b = *(const float4*)(bias2 + lane * 4);
    const float h0 = fmaxf(ax * inv + b.x, 0.0f);
    const float h1 = fmaxf(ay * inv + b.y, 0.0f);
    const float h2 = fmaxf(az * inv + b.z, 0.0f);
    const float h3 = fmaxf(aw * inv + b.w, 0.0f);
    // fused FC: out[d][c] = h . Wfc[c] + bfc[c]
#pragma unroll
    for (int c = 0; c < NCLS; c++) {
        const float4 wv = __ldg((const float4*)(Wfc + c * 128 + lane * 4));
        float p = h0 * wv.x + h1 * wv.y + h2 * wv.z + h3 * wv.w;
#pragma unroll
        for (int o = 16; o > 0; o >>= 1) p += __shfl_xor_sync(0xffffffffu, p, o);
        if (lane == 0) out[(size_t)d * NCLS + c] = p + bfc[c];
    }
}

#define GEMM1_SMEM ((64 * 260 + 64 * 520) * 4)
#define GEMM2_SMEM ((64 * 516 + 64 * 136) * 4)

extern "C" void kernel_launch(void* const* d_in, const int* in_sizes, int n_in,
                              void* d_out, int out_size) {
    const float* x      = (const float*)d_in[0];
    const int*   lens   = (const int*)d_in[1];
    const int*   ei     = (const int*)d_in[2];
    const float* Wih_f  = (const float*)d_in[3];
    const float* Whh_f  = (const float*)d_in[4];
    const float* b_f    = (const float*)d_in[5];
    const float* Wih_b  = (const float*)d_in[6];
    const float* Whh_b  = (const float*)d_in[7];
    const float* b_b    = (const float*)d_in[8];
    const float* W1     = (const float*)d_in[9];
    const float* a1s    = (const float*)d_in[10];
    const float* a1d    = (const float*)d_in[11];
    const float* bias1  = (const float*)d_in[12];
    const float* W2     = (const float*)d_in[13];
    const float* a2s    = (const float*)d_in[14];
    const float* a2d    = (const float*)d_in[15];
    const float* bias2  = (const float*)d_in[16];
    const float* Wfc    = (const float*)d_in[17];
    const float* bfc    = (const float*)d_in[18];
    float* out = (float*)d_out;

    float *p_hcat, *p_xh1, *p_al1s, *p_al1d, *p_agg1, *p_xh2, *p_al2s, *p_al2d;
    float *p_W1t, *p_W2t;
    cudaGetSymbolAddress((void**)&p_hcat, g_hcat);
    cudaGetSymbolAddress((void**)&p_xh1,  g_xh1);
    cudaGetSymbolAddress((void**)&p_al1s, g_al1s);
    cudaGetSymbolAddress((void**)&p_al1d, g_al1d);
    cudaGetSymbolAddress((void**)&p_agg1, g_agg1);
    cudaGetSymbolAddress((void**)&p_xh2,  g_xh2);
    cudaGetSymbolAddress((void**)&p_al2s, g_al2s);
    cudaGetSymbolAddress((void**)&p_al2d, g_al2d);
    cudaGetSymbolAddress((void**)&p_W1t,  g_W1t);
    cudaGetSymbolAddress((void**)&p_W2t,  g_W2t);

    cudaFuncSetAttribute(lstm_mma, cudaFuncAttributeMaxDynamicSharedMemorySize, LSTM_SMEM);
    cudaFuncSetAttribute(gemm_mma<256, 512>, cudaFuncAttributeMaxDynamicSharedMemorySize, GEMM1_SMEM);
    cudaFuncSetAttribute(gemm_mma<512, 128>, cudaFuncAttributeMaxDynamicSharedMemorySize, GEMM2_SMEM);

    // weight prep + CSR build (independent of LSTM)
    prep_w<<<1024, 256>>>(Wih_f, Whh_f, Wih_b, Whh_b);
    prep_gw<<<(256 * 512 + 512 * 128 + 255) / 256, 256>>>(W1, W2);
    csr_zero<<<(NN + 255) / 256, 256>>>();
    csr_hist<<<(EN + 255) / 256, 256>>>(ei);
    csr_scan<<<1, 1024>>>();
    csr_scatter<<<(EN + 255) / 256, 256>>>(ei);

    // BiLSTM
    lstm_mma<<<dim3(313, 2), 512, LSTM_SMEM>>>(x, lens, b_f, b_b);

    // GAT layer 1
    gemm_mma<256, 512><<<313, 512, GEMM1_SMEM>>>(p_hcat, p_W1t, p_xh1);
    gat_al<4><<<NN * 4 / 8, 256>>>(p_xh1, a1s, a1d, p_al1s, p_al1d);
    gat_gather4<<<(NN * 4 + 7) / 8, 256>>>(bias1);

    // GAT layer 2
    gemm_mma<512, 128><<<313, 512, GEMM2_SMEM>>>(p_agg1, p_W2t, p_xh2);
    gat_al<1><<<(NN + 7) / 8, 256>>>(p_xh2, a2s, a2d, p_al2s, p_al2d);
    gat_gather1_fc<<<(NN + 7) / 8, 256>>>(bias2, Wfc, bfc, out);
}

// round 9
// speedup vs baseline: 3.3002x; 1.0842x over previous
#include <cuda_runtime.h>
#include <math.h>
#include <stdint.h>

#define NN 20000
#define TT 20
#define FF 128
#define HH 128
#define GHD 128
#define NHEADS 4
#define NCLS 10
#define EE 640000
#define EN (EE + NN)

// ---------------- scratch (device globals: allocation-free rule) ----------------
__device__ float g_hcat[NN * 256];
__device__ float g_xh1[NN * 512];
__device__ float g_al1s[NN * 4];
__device__ float g_al1d[NN * 4];
__device__ float g_agg1[NN * 512];
__device__ float g_xh2[NN * 128];
__device__ float g_al2s[NN];
__device__ float g_al2d[NN];
// LSTM weights tf32-rounded: [dir][k=256][gatecol=512]
__device__ float g_Wt[2 * 256 * 512];
// GAT weights tf32-rounded, [k][col]
__device__ float g_W1t[256 * 512];
__device__ float g_W2t[512 * 128];
// CSR by dst
__device__ int g_cnt[NN];
__device__ int g_base[NN + 1];
__device__ int g_srcs[EN];

__device__ __forceinline__ float lrelu(float x) { return x > 0.0f ? x : 0.2f * x; }
__device__ __forceinline__ float rna_tf32(float v) {
    float o; asm("cvt.rna.tf32.f32 %0, %1;" : "=f"(o) : "f"(v)); return o;
}
__device__ __forceinline__ float fsig(float x) { return __fdividef(1.0f, 1.0f + __expf(-x)); }
__device__ __forceinline__ float ftanh(float x) {
    return __fdividef(2.0f, 1.0f + __expf(-2.0f * x)) - 1.0f;
}
__device__ __forceinline__ uint32_t smem_u32(const void* p) {
    uint32_t a;
    asm("{ .reg .u64 t; cvta.to.shared.u64 t, %1; cvt.u32.u64 %0, t; }" : "=r"(a) : "l"(p));
    return a;
}
#define CP16(dst, src)    asm volatile("cp.async.cg.shared.global [%0], [%1], 16;" :: "r"(dst), "l"(src))
#define CP_COMMIT()       asm volatile("cp.async.commit_group;" ::: "memory")
#define CP_WAIT0()        asm volatile("cp.async.wait_group 0;" ::: "memory")

// m16n8k8 tf32 mma: D += A*B. A row-major, B col-major (k x n).
__device__ __forceinline__ void mma_tf32(float* d, uint32_t a0, uint32_t a1, uint32_t a2,
                                         uint32_t a3, uint32_t b0, uint32_t b1) {
    asm volatile("mma.sync.aligned.m16n8k8.row.col.f32.tf32.tf32.f32 "
                 "{%0,%1,%2,%3}, {%4,%5,%6,%7}, {%8,%9}, {%0,%1,%2,%3};"
                 : "+f"(d[0]), "+f"(d[1]), "+f"(d[2]), "+f"(d[3])
                 : "r"(a0), "r"(a1), "r"(a2), "r"(a3), "r"(b0), "r"(b1));
}

// ---------------- weight prep ----------------
__global__ void prep_w(const float* __restrict__ Wih_f, const float* __restrict__ Whh_f,
                       const float* __restrict__ Wih_b, const float* __restrict__ Whh_b) {
    const int idx = blockIdx.x * blockDim.x + threadIdx.x;
    if (idx >= 2 * 256 * 512) return;
    const int dir = idx >> 17;
    const int rem = idx & 131071;
    const int k = rem >> 9;
    const int c = rem & 511;
    const float* Ws = dir ? (k < 128 ? Wih_b : Whh_b) : (k < 128 ? Wih_f : Whh_f);
    g_Wt[idx] = rna_tf32(Ws[(size_t)c * 128 + (k & 127)]);
}
__global__ void prep_gw(const float* __restrict__ W1, const float* __restrict__ W2) {
    const int idx = blockIdx.x * blockDim.x + threadIdx.x;
    if (idx < 256 * 512) {
        const int k = idx >> 9, c = idx & 511;
        g_W1t[idx] = rna_tf32(W1[(size_t)c * 256 + k]);
    }
    const int j = idx - 256 * 512;
    if (j >= 0 && j < 512 * 128) {
        const int k = j >> 7, c = j & 127;
        g_W2t[j] = rna_tf32(W2[(size_t)c * 512 + k]);
    }
}

// ---------------- CSR build (edges + self loops, grouped by dst) ----------------
__global__ void csr_zero() {
    const int i = blockIdx.x * blockDim.x + threadIdx.x;
    if (i < NN) g_cnt[i] = 0;
}
__global__ void csr_hist(const int* __restrict__ ei) {
    const int e = blockIdx.x * blockDim.x + threadIdx.x;
    if (e >= EN) return;
    const int d = (e < EE) ? ei[EE + e] : (e - EE);
    atomicAdd(&g_cnt[d], 1);
}
__global__ void __launch_bounds__(1024, 1) csr_scan() {
    __shared__ int ps[1024];
    const int tid = threadIdx.x;
    const int base = tid * 20;
    int local[20];
    int s = 0;
#pragma unroll
    for (int i = 0; i < 20; i++) {
        const int idx = base + i;
        const int c = (idx < NN) ? g_cnt[idx] : 0;
        local[i] = s;
        s += c;
    }
    ps[tid] = s;
    __syncthreads();
    for (int off = 1; off < 1024; off <<= 1) {
        int v = (tid >= off) ? ps[tid - off] : 0;
        __syncthreads();
        ps[tid] += v;
        __syncthreads();
    }
    const int excl = (tid == 0) ? 0 : ps[tid - 1];
#pragma unroll
    for (int i = 0; i < 20; i++) {
        const int idx = base + i;
        if (idx < NN) g_base[idx] = excl + local[i];
    }
    if (tid == 1023) g_base[NN] = ps[1023];
    __syncthreads();
    for (int i = tid; i < NN; i += 1024) g_cnt[i] = g_base[i];  // cursor
}
__global__ void csr_scatter(const int* __restrict__ ei) {
    const int e = blockIdx.x * blockDim.x + threadIdx.x;
    if (e >= EN) return;
    int s, d;
    if (e < EE) { s = ei[e]; d = ei[EE + e]; } else { s = d = e - EE; }
    const int pos = atomicAdd(&g_cnt[d], 1);
    g_srcs[pos] = s;
}

// ---------------- tensor-core BiLSTM via mma.sync tf32 ----------------
// 32 seqs/CTA, 256 threads (8 warps), 2 CTAs/SM for latency hiding.
// Warp (m = wid>>2, q = wid&3): rows m*16..+15, hidden cols q*32..+31, all 4 gates.
// A smem: [32][260] (x cols 0-127, h cols 128-255). B: K=16 chunks [16][520] x2 (cp.async).
#define SA 260
#define SB 520
#define BOFF 8320
#define BIASOFF 24960
#define LENOFF 25472
#define LSTM_SMEM (25504 * 4)

__global__ void __launch_bounds__(256, 2) lstm_mma(
    const float* __restrict__ x, const int* __restrict__ lengths,
    const float* __restrict__ b_f, const float* __restrict__ b_b)
{
    extern __shared__ float sm[];
    float* const A_s   = sm;
    float* const B_s   = sm + 8320;           // 2 x [16][520]
    float* const biasf = sm + BIASOFF;
    int*   const len_s = (int*)(sm + LENOFF);
    const uint32_t B_u = smem_u32(B_s);

    const int tid = threadIdx.x;
    const int wid = tid >> 5, lane = tid & 31;
    const int g = lane >> 2, ctg = lane & 3;
    const int dir = blockIdx.y;
    const int seq0 = blockIdx.x * 32;
    const float* __restrict__ bb = dir ? b_b : b_f;
    const float* __restrict__ Wt = g_Wt + (size_t)dir * 131072;

    const int r0 = (wid >> 2) * 16;
    const int q  = wid & 3;
    const int rA = r0 + g, rB = r0 + g + 8;

    biasf[tid] = bb[tid];
    biasf[tid + 256] = bb[tid + 256];
    if (tid < 32) len_s[tid] = lengths[seq0 + tid];
    for (int i = tid; i < 32 * 128; i += 256)
        A_s[(i >> 7) * SA + 128 + (i & 127)] = 0.0f;
    __syncthreads();

    const int lenA = len_s[rA], lenB = len_s[rB];

    float acc[4][4][4];
    float cst[4][4];
#pragma unroll
    for (int ni = 0; ni < 4; ni++)
#pragma unroll
        for (int p = 0; p < 4; p++) cst[ni][p] = 0.0f;

    for (int t = 0; t < TT; t++) {
        // stage x_t (tf32-rounded) into A cols 0..127
#pragma unroll
        for (int j = 0; j < 4; j++) {
            const int idx = j * 256 + tid;
            const int row = idx >> 5, f4 = idx & 31;
            const int ls = len_s[row];
            const int ttv = dir ? max(ls - 1 - t, 0) : t;
            const float4 v = *(const float4*)(x + ((size_t)(seq0 + row) * TT + ttv) * FF + f4 * 4);
            float4 r;
            r.x = rna_tf32(v.x); r.y = rna_tf32(v.y);
            r.z = rna_tf32(v.z); r.w = rna_tf32(v.w);
            *(float4*)(A_s + row * SA + f4 * 4) = r;
        }
#pragma unroll
        for (int gi = 0; gi < 4; gi++)
#pragma unroll
            for (int ni = 0; ni < 4; ni++)
#pragma unroll
                for (int p = 0; p < 4; p++) acc[gi][ni][p] = 0.0f;

        // prefetch B chunk 0 (16 rows x 512 cols)
#pragma unroll
        for (int j = 0; j < 8; j++) {
            const int idx = j * 256 + tid;
            const int row = idx >> 7, f4 = idx & 127;
            CP16(B_u + (row * SB + f4 * 4) * 4, Wt + row * 512 + f4 * 4);
        }
        CP_COMMIT();

        for (int kc = 0; kc < 16; kc++) {
            CP_WAIT0();
            __syncthreads();
            if (kc < 15) {
                const int nb = (kc + 1) & 1;
                const float* src = Wt + (kc + 1) * 8192;
#pragma unroll
                for (int j = 0; j < 8; j++) {
                    const int idx = j * 256 + tid;
                    const int row = idx >> 7, f4 = idx & 127;
                    CP16(B_u + (nb * BOFF + row * SB + f4 * 4) * 4, src + row * 512 + f4 * 4);
                }
                CP_COMMIT();
            }
            const float* Bb = B_s + (kc & 1) * BOFF;
#pragma unroll
            for (int ks = 0; ks < 2; ks++) {
                const int k = kc * 16 + ks * 8;
                const uint32_t a0 = __float_as_uint(A_s[rA * SA + k + ctg]);
                const uint32_t a1 = __float_as_uint(A_s[rB * SA + k + ctg]);
                const uint32_t a2 = __float_as_uint(A_s[rA * SA + k + ctg + 4]);
                const uint32_t a3 = __float_as_uint(A_s[rB * SA + k + ctg + 4]);
                const float* B0 = Bb + (ks * 8 + ctg) * SB + g;
                const float* B4 = B0 + 4 * SB;
#pragma unroll
                for (int gi = 0; gi < 4; gi++) {
#pragma unroll
                    for (int ni = 0; ni < 4; ni++) {
                        const int n0 = gi * 128 + q * 32 + ni * 8;
                        const uint32_t b0 = __float_as_uint(B0[n0]);
                        const uint32_t b1 = __float_as_uint(B4[n0]);
                        mma_tf32(acc[gi][ni], a0, a1, a2, a3, b0, b1);
                    }
                }
            }
        }

        __syncthreads();   // all mma reads of A_s h-region done before h writeback

        // epilogue: cell math (register-local), h writeback
#pragma unroll
        for (int ni = 0; ni < 4; ni++) {
            const int hc0 = q * 32 + ni * 8 + 2 * ctg;
#pragma unroll
            for (int p = 0; p < 4; p++) {
                const int col = hc0 + (p & 1);
                const int row = (p < 2) ? rA : rB;
                const bool act = t < ((p < 2) ? lenA : lenB);
                const float pi = acc[0][ni][p] + biasf[col];
                const float pf = acc[1][ni][p] + biasf[128 + col];
                const float pg = acc[2][ni][p] + biasf[256 + col];
                const float po = acc[3][ni][p] + biasf[384 + col];
                const float cn = fsig(pf) * cst[ni][p] + fsig(pi) * ftanh(pg);
                const float hn = fsig(po) * ftanh(cn);
                if (act) {
                    cst[ni][p] = cn;
                    A_s[row * SA + 128 + col] = rna_tf32(hn);
                }
            }
        }
        __syncthreads();   // h visible before next step (or final copy)
    }

    // final frozen h -> g_hcat
    for (int i = tid; i < 32 * 32; i += 256) {
        const int row = i >> 5, f4 = i & 31;
        const float4 v = *(const float4*)(A_s + row * SA + 128 + f4 * 4);
        *(float4*)(g_hcat + (size_t)(seq0 + row) * 256 + dir * 128 + f4 * 4) = v;
    }
}

// ---------------- generic tensor GEMM: C[N][COLS] = A[N][KTOT] @ Bt[KTOT][COLS] ----------------
template <int KTOT, int COLS>
__global__ void __launch_bounds__(512, 1) gemm_mma(
    const float* __restrict__ A, const float* __restrict__ Bt, float* __restrict__ C)
{
    constexpr int SA2 = KTOT + 4;
    constexpr int SB2 = COLS + 8;
    constexpr int GI = COLS / 128;
    constexpr int BO2 = 32 * SB2;
    extern __shared__ float sm[];
    float* const A_s = sm;
    float* const B_s = sm + 64 * SA2;
    const uint32_t B_u = smem_u32(B_s);

    const int tid = threadIdx.x;
    const int wid = tid >> 5, lane = tid & 31;
    const int g = lane >> 2, ctg = lane & 3;
    const int r0 = (wid >> 2) * 16;
    const int q = wid & 3;
    const int rA = r0 + g, rB = r0 + g + 8;
    const int row0 = blockIdx.x * 64;

    constexpr int K4 = KTOT / 4;
    for (int idx = tid; idx < 64 * K4; idx += 512) {
        const int row = idx / K4, c4 = idx % K4;
        const int sq = min(row0 + row, NN - 1);
        const float4 v = *(const float4*)(A + (size_t)sq * KTOT + c4 * 4);
        float4 r;
        r.x = rna_tf32(v.x); r.y = rna_tf32(v.y);
        r.z = rna_tf32(v.z); r.w = rna_tf32(v.w);
        *(float4*)(A_s + row * SA2 + c4 * 4) = r;
    }

    float acc[GI][4][4];
#pragma unroll
    for (int gi = 0; gi < GI; gi++)
#pragma unroll
        for (int ni = 0; ni < 4; ni++)
#pragma unroll
            for (int p = 0; p < 4; p++) acc[gi][ni][p] = 0.0f;

    constexpr int NC = KTOT / 32;
    constexpr int C4 = COLS / 4;
    for (int j = tid; j < 8 * COLS; j += 512) {
        const int row = j / C4, c4 = j % C4;
        CP16(B_u + (row * SB2 + c4 * 4) * 4, Bt + (size_t)row * COLS + c4 * 4);
    }
    CP_COMMIT();

    for (int kc = 0; kc < NC; kc++) {
        CP_WAIT0();
        __syncthreads();
        if (kc < NC - 1) {
            const int nb = (kc + 1) & 1;
            const float* src = Bt + (size_t)(kc + 1) * 32 * COLS;
            for (int j = tid; j < 8 * COLS; j += 512) {
                const int row = j / C4, c4 = j % C4;
                CP16(B_u + (nb * BO2 + row * SB2 + c4 * 4) * 4, src + (size_t)row * COLS + c4 * 4);
            }
            CP_COMMIT();
        }
        const float* Bb = B_s + (kc & 1) * BO2;
#pragma unroll
        for (int ks = 0; ks < 4; ks++) {
            const int k = kc * 32 + ks * 8;
            const uint32_t a0 = __float_as_uint(A_s[rA * SA2 + k + ctg]);
            const uint32_t a1 = __float_as_uint(A_s[rB * SA2 + k + ctg]);
            const uint32_t a2 = __float_as_uint(A_s[rA * SA2 + k + ctg + 4]);
            const uint32_t a3 = __float_as_uint(A_s[rB * SA2 + k + ctg + 4]);
            const float* B0 = Bb + (ks * 8 + ctg) * SB2 + g;
            const float* B4 = B0 + 4 * SB2;
#pragma unroll
            for (int gi = 0; gi < GI; gi++) {
#pragma unroll
                for (int ni = 0; ni < 4; ni++) {
                    const int n0 = gi * 128 + q * 32 + ni * 8;
                    const uint32_t b0 = __float_as_uint(B0[n0]);
                    const uint32_t b1 = __float_as_uint(B4[n0]);
                    mma_tf32(acc[gi][ni], a0, a1, a2, a3, b0, b1);
                }
            }
        }
    }

#pragma unroll
    for (int gi = 0; gi < GI; gi++)
#pragma unroll
        for (int ni = 0; ni < 4; ni++) {
            const int n0 = gi * 128 + q * 32 + ni * 8 + 2 * ctg;
            if (row0 + rA < NN)
                *(float2*)(C + (size_t)(row0 + rA) * COLS + n0) =
                    make_float2(acc[gi][ni][0], acc[gi][ni][1]);
            if (row0 + rB < NN)
                *(float2*)(C + (size_t)(row0 + rB) * COLS + n0) =
                    make_float2(acc[gi][ni][2], acc[gi][ni][3]);
        }
}

// ---------------- GAT attention-logit projections (warp per (node, head)) ----------------
template <int NH>
__global__ void gat_al(const float* __restrict__ xh, const float* __restrict__ asrc,
                       const float* __restrict__ adst, float* __restrict__ als,
                       float* __restrict__ ald)
{
    const int w = (blockIdx.x * blockDim.x + threadIdx.x) >> 5;
    const int lane = threadIdx.x & 31;
    if (w >= NN * NH) return;
    const int n = w / NH, h = w % NH;
    const float4 v  = *(const float4*)(xh + (size_t)n * (NH * GHD) + h * GHD + lane * 4);
    const float4 s4 = *(const float4*)(asrc + h * GHD + lane * 4);
    const float4 d4 = *(const float4*)(adst + h * GHD + lane * 4);
    float s = v.x * s4.x + v.y * s4.y + v.z * s4.z + v.w * s4.w;
    float d = v.x * d4.x + v.y * d4.y + v.z * d4.z + v.w * d4.w;
#pragma unroll
    for (int o = 16; o > 0; o >>= 1) {
        s += __shfl_xor_sync(0xffffffffu, s, o);
        d += __shfl_xor_sync(0xffffffffu, d, o);
    }
    if (lane == 0) { als[w] = s; ald[w] = d; }
}

// ---------------- layer-1 gather: warp per (dst, head), lane-parallel edge prologue ----------------
__global__ void gat_gather4(const float* __restrict__ bias1) {
    const int w = (blockIdx.x * blockDim.x + threadIdx.x) >> 5;
    const int lane = threadIdx.x & 31;
    if (w >= NN * NHEADS) return;
    const int d = w >> 2, h = w & 3;
    const float aldv = g_al1d[d * 4 + h];
    const int beg = g_base[d], end = g_base[d + 1];
    float ax = 0.0f, ay = 0.0f, az = 0.0f, aw = 0.0f, denp = 0.0f;
    for (int eb = beg; eb < end; eb += 32) {
        const int ne = end - eb;
        int sl = 0; float eel = 0.0f;
        if (lane < ne) {
            sl = g_srcs[eb + lane];
            eel = __expf(lrelu(g_al1s[sl * 4 + h] + aldv));
        }
        denp += eel;
        const int m = min(ne, 32);
#pragma unroll 4
        for (int j = 0; j < m; j++) {
            const int s = __shfl_sync(0xffffffffu, sl, j);
            const float ee = __shfl_sync(0xffffffffu, eel, j);
            const float4 v = *(const float4*)(g_xh1 + (size_t)s * 512 + h * GHD + lane * 4);
            ax += ee * v.x; ay += ee * v.y; az += ee * v.z; aw += ee * v.w;
        }
    }
    float den = denp;
#pragma unroll
    for (int o = 16; o > 0; o >>= 1) den += __shfl_xor_sync(0xffffffffu, den, o);
    const float inv = __fdividef(1.0f, den + 1e-16f);
    const float4 b = *(const float4*)(bias1 + h * GHD + lane * 4);
    float4 o;
    o.x = fmaxf(ax * inv + b.x, 0.0f);
    o.y = fmaxf(ay * inv + b.y, 0.0f);
    o.z = fmaxf(az * inv + b.z, 0.0f);
    o.w = fmaxf(aw * inv + b.w, 0.0f);
    *(float4*)(g_agg1 + (size_t)d * 512 + h * GHD + lane * 4) = o;
}

// ---------------- layer-2 gather + fused FC: warp per dst ----------------
__global__ void gat_gather1_fc(const float* __restrict__ bias2,
                               const float* __restrict__ Wfc, const float* __restrict__ bfc,
                               float* __restrict__ out) {
    const int w = (blockIdx.x * blockDim.x + threadIdx.x) >> 5;
    const int lane = threadIdx.x & 31;
    if (w >= NN) return;
    const int d = w;
    const float aldv = g_al2d[d];
    const int beg = g_base[d], end = g_base[d + 1];
    float ax = 0.0f, ay = 0.0f, az = 0.0f, aw = 0.0f, denp = 0.0f;
    for (int eb = beg; eb < end; eb += 32) {
        const int ne = end - eb;
        int sl = 0; float eel = 0.0f;
        if (lane < ne) {
            sl = g_srcs[eb + lane];
            eel = __expf(lrelu(g_al2s[sl] + aldv));
        }
        denp += eel;
        const int m = min(ne, 32);
#pragma unroll 4
        for (int j = 0; j < m; j++) {
            const int s = __shfl_sync(0xffffffffu, sl, j);
            const float ee = __shfl_sync(0xffffffffu, eel, j);
            const float4 v = *(const float4*)(g_xh2 + (size_t)s * 128 + lane * 4);
            ax += ee * v.x; ay += ee * v.y; az += ee * v.z; aw += ee * v.w;
        }
    }
    float den = denp;
#pragma unroll
    for (int o = 16; o > 0; o >>= 1) den += __shfl_xor_sync(0xffffffffu, den, o);
    const float inv = __fdividef(1.0f, den + 1e-16f);
    const float4 b = *(const float4*)(bias2 + lane * 4);
    const float h0 = fmaxf(ax * inv + b.x, 0.0f);
    const float h1 = fmaxf(ay * inv + b.y, 0.0f);
    const float h2 = fmaxf(az * inv + b.z, 0.0f);
    const float h3 = fmaxf(aw * inv + b.w, 0.0f);
#pragma unroll
    for (int c = 0; c < NCLS; c++) {
        const float4 wv = __ldg((const float4*)(Wfc + c * 128 + lane * 4));
        float p = h0 * wv.x + h1 * wv.y + h2 * wv.z + h3 * wv.w;
#pragma unroll
        for (int o = 16; o > 0; o >>= 1) p += __shfl_xor_sync(0xffffffffu, p, o);
        if (lane == 0) out[(size_t)d * NCLS + c] = p + bfc[c];
    }
}

#define GEMM1_SMEM ((64 * 260 + 64 * 520) * 4)
#define GEMM2_SMEM ((64 * 516 + 64 * 136) * 4)

extern "C" void kernel_launch(void* const* d_in, const int* in_sizes, int n_in,
                              void* d_out, int out_size) {
    const float* x      = (const float*)d_in[0];
    const int*   lens   = (const int*)d_in[1];
    const int*   ei     = (const int*)d_in[2];
    const float* Wih_f  = (const float*)d_in[3];
    const float* Whh_f  = (const float*)d_in[4];
    const float* b_f    = (const float*)d_in[5];
    const float* Wih_b  = (const float*)d_in[6];
    const float* Whh_b  = (const float*)d_in[7];
    const float* b_b    = (const float*)d_in[8];
    const float* W1     = (const float*)d_in[9];
    const float* a1s    = (const float*)d_in[10];
    const float* a1d    = (const float*)d_in[11];
    const float* bias1  = (const float*)d_in[12];
    const float* W2     = (const float*)d_in[13];
    const float* a2s    = (const float*)d_in[14];
    const float* a2d    = (const float*)d_in[15];
    const float* bias2  = (const float*)d_in[16];
    const float* Wfc    = (const float*)d_in[17];
    const float* bfc    = (const float*)d_in[18];
    float* out = (float*)d_out;

    float *p_hcat, *p_xh1, *p_al1s, *p_al1d, *p_agg1, *p_xh2, *p_al2s, *p_al2d;
    float *p_W1t, *p_W2t;
    cudaGetSymbolAddress((void**)&p_hcat, g_hcat);
    cudaGetSymbolAddress((void**)&p_xh1,  g_xh1);
    cudaGetSymbolAddress((void**)&p_al1s, g_al1s);
    cudaGetSymbolAddress((void**)&p_al1d, g_al1d);
    cudaGetSymbolAddress((void**)&p_agg1, g_agg1);
    cudaGetSymbolAddress((void**)&p_xh2,  g_xh2);
    cudaGetSymbolAddress((void**)&p_al2s, g_al2s);
    cudaGetSymbolAddress((void**)&p_al2d, g_al2d);
    cudaGetSymbolAddress((void**)&p_W1t,  g_W1t);
    cudaGetSymbolAddress((void**)&p_W2t,  g_W2t);

    cudaFuncSetAttribute(lstm_mma, cudaFuncAttributeMaxDynamicSharedMemorySize, LSTM_SMEM);
    cudaFuncSetAttribute(gemm_mma<256, 512>, cudaFuncAttributeMaxDynamicSharedMemorySize, GEMM1_SMEM);
    cudaFuncSetAttribute(gemm_mma<512, 128>, cudaFuncAttributeMaxDynamicSharedMemorySize, GEMM2_SMEM);

    // weight prep + CSR build (independent of LSTM)
    prep_w<<<1024, 256>>>(Wih_f, Whh_f, Wih_b, Whh_b);
    prep_gw<<<(256 * 512 + 512 * 128 + 255) / 256, 256>>>(W1, W2);
    csr_zero<<<(NN + 255) / 256, 256>>>();
    csr_hist<<<(EN + 255) / 256, 256>>>(ei);
    csr_scan<<<1, 1024>>>();
    csr_scatter<<<(EN + 255) / 256, 256>>>(ei);

    // BiLSTM
    lstm_mma<<<dim3(625, 2), 256, LSTM_SMEM>>>(x, lens, b_f, b_b);

    // GAT layer 1
    gemm_mma<256, 512><<<313, 512, GEMM1_SMEM>>>(p_hcat, p_W1t, p_xh1);
    gat_al<4><<<NN * 4 / 8, 256>>>(p_xh1, a1s, a1d, p_al1s, p_al1d);
    gat_gather4<<<(NN * 4 + 7) / 8, 256>>>(bias1);

    // GAT layer 2
    gemm_mma<512, 128><<<313, 512, GEMM2_SMEM>>>(p_agg1, p_W2t, p_xh2);
    gat_al<1><<<(NN + 7) / 8, 256>>>(p_xh2, a2s, a2d, p_al2s, p_al2d);
    gat_gather1_fc<<<(NN + 7) / 8, 256>>>(bias2, Wfc, bfc, out);
}